// round 2
// baseline (speedup 1.0000x reference)
#include <cuda_runtime.h>
#include <cstdint>

#define D       64
#define K       1024
#define HW      4096
#define TILE    128
#define BLOCK   128
#define MAXBLK  4096

__device__ float g_cnorm[K];
__device__ float g_partials[MAXBLK];

__device__ __forceinline__ unsigned long long ffma2(unsigned long long a,
                                                    unsigned long long b,
                                                    unsigned long long c) {
    unsigned long long d;
    asm("fma.rn.f32x2 %0, %1, %2, %3;" : "=l"(d) : "l"(a), "l"(b), "l"(c));
    return d;
}
__device__ __forceinline__ float lo2(unsigned long long v) {
    return __uint_as_float((unsigned)(v & 0xffffffffull));
}
__device__ __forceinline__ float hi2(unsigned long long v) {
    return __uint_as_float((unsigned)(v >> 32));
}
__device__ __forceinline__ unsigned long long pack2(float lo, float hi) {
    return ((unsigned long long)__float_as_uint(hi) << 32) |
           (unsigned long long)__float_as_uint(lo);
}

// ||c_k||^2, strictly sequential mul-then-add (emulates XLA CPU reduce)
__global__ void cnorm_kernel(const float* __restrict__ cb) {
    int k = blockIdx.x * blockDim.x + threadIdx.x;
    if (k < K) {
        float s = 0.f;
#pragma unroll
        for (int d = 0; d < D; d++) {
            float v = cb[k * D + d];
            s = __fadd_rn(s, __fmul_rn(v, v));
        }
        g_cnorm[k] = s;
    }
}

// One thread per point. Bit-exact emulation of:
//   dist_k = fl( fl(znorm + cnorm_k) - fl(2 * dot_k) )
// with znorm = sequential mul+add over d, dot_k = sequential fma over d,
// argmin = first minimum (strict <, ascending k).
__global__ void __launch_bounds__(BLOCK, 2)
vq_kernel(const float* __restrict__ z,
          const float* __restrict__ cb,
          float* __restrict__ out,
          long long idxOff) {
    __shared__ float sCt[D][TILE];   // transposed tile: dim-major
    __shared__ float sN[TILE];
    __shared__ float sRed[BLOCK / 32];

    const int tid = threadIdx.x;
    const int n = blockIdx.x * BLOCK + tid;
    const int b = n >> 12;            // n / HW
    const int hw = n & (HW - 1);      // n % HW

    // Load z features; keep duplicated-lane packed copies for f32x2 FMA.
    const float* zbase = z + (size_t)b * D * HW + hw;
    unsigned long long zdup[D];
#pragma unroll
    for (int d = 0; d < D; d++) {
        float v = zbase[(size_t)d * HW];
        zdup[d] = pack2(v, v);
    }

    // znorm: sequential fp32 mul-then-add, ascending d
    float zn = 0.f;
#pragma unroll
    for (int d = 0; d < D; d++) {
        float v = lo2(zdup[d]);
        zn = __fadd_rn(zn, __fmul_rn(v, v));
    }

    float best = 3.4e38f;
    int bestk = 0;

#pragma unroll 1
    for (int t = 0; t < K / TILE; t++) {
        // cooperative transposed tile load
        const float* src = cb + (size_t)t * TILE * D;
#pragma unroll
        for (int j = 0; j < (TILE * D) / BLOCK; j++) {
            int idx = tid + j * BLOCK;
            sCt[idx & (D - 1)][idx >> 6] = src[idx];
        }
        sN[tid] = g_cnorm[t * TILE + tid];
        __syncthreads();

#pragma unroll 1
        for (int c = 0; c < TILE; c += 8) {
            unsigned long long a0 = 0ull, a1 = 0ull, a2 = 0ull, a3 = 0ull;
#pragma unroll
            for (int d = 0; d < D; d++) {
                ulonglong2 v0 = *(const ulonglong2*)&sCt[d][c];
                ulonglong2 v1 = *(const ulonglong2*)&sCt[d][c + 4];
                a0 = ffma2(zdup[d], v0.x, a0);
                a1 = ffma2(zdup[d], v0.y, a1);
                a2 = ffma2(zdup[d], v1.x, a2);
                a3 = ffma2(zdup[d], v1.y, a3);
            }
            float dots[8];
            dots[0] = lo2(a0); dots[1] = hi2(a0);
            dots[2] = lo2(a1); dots[3] = hi2(a1);
            dots[4] = lo2(a2); dots[5] = hi2(a2);
            dots[6] = lo2(a3); dots[7] = hi2(a3);
#pragma unroll
            for (int i = 0; i < 8; i++) {
                float t1 = __fadd_rn(zn, sN[c + i]);
                float t2 = __fmul_rn(2.0f, dots[i]);
                float dist = __fsub_rn(t1, t2);
                if (dist < best) { best = dist; bestk = t * TILE + c + i; }
            }
        }
        __syncthreads();
    }

    // Gather chosen code, emulate z_q_st = fl(z + fl(z_q - z)), loss terms
    const float4* crow = (const float4*)(cb + (size_t)bestk * D);
    float* outz = out + (size_t)b * D * HW + hw;
    float sumsq = 0.f;
#pragma unroll
    for (int i = 0; i < 16; i++) {
        float4 q = __ldg(&crow[i]);
        float zv[4];
        zv[0] = lo2(zdup[2 * i]);
        zv[1] = hi2(zdup[2 * i]);
        zv[2] = lo2(zdup[2 * i + 1]);
        zv[3] = hi2(zdup[2 * i + 1]);
        float qq[4] = {q.x, q.y, q.z, q.w};
#pragma unroll
        for (int j = 0; j < 4; j++) {
            float dd = __fsub_rn(qq[j], zv[j]);
            float ov = __fadd_rn(zv[j], dd);
            sumsq += __fmul_rn(dd, dd);
            outz[(size_t)(4 * i + j) * HW] = ov;
        }
    }

    if (idxOff >= 0) out[idxOff + n] = (float)bestk;

    // deterministic block reduction of sumsq
#pragma unroll
    for (int off = 16; off > 0; off >>= 1)
        sumsq += __shfl_down_sync(0xffffffffu, sumsq, off);
    if ((tid & 31) == 0) sRed[tid >> 5] = sumsq;
    __syncthreads();
    if (tid == 0) {
        float tot = 0.f;
#pragma unroll
        for (int w = 0; w < BLOCK / 32; w++) tot += sRed[w];
        g_partials[blockIdx.x] = tot;
    }
}

__global__ void loss_kernel(float* __restrict__ out, int nBlocks,
                            long long lossOff, float invN) {
    __shared__ float s[512];
    int tid = threadIdx.x;
    float v = 0.f;
    for (int i = tid; i < nBlocks; i += 512) v += g_partials[i];
    s[tid] = v;
    __syncthreads();
    for (int st = 256; st > 0; st >>= 1) {
        if (tid < st) s[tid] += s[tid + st];
        __syncthreads();
    }
    if (tid == 0 && lossOff >= 0) {
        float m = __fmul_rn(s[0], invN);              // exact: invN = 2^-23
        out[lossOff] = __fadd_rn(m, __fmul_rn(0.25f, m));
    }
}

extern "C" void kernel_launch(void* const* d_in, const int* in_sizes, int n_in,
                              void* d_out, int out_size) {
    const float* z = (const float*)d_in[0];
    const float* cb = (const float*)d_in[1];
    float* out = (float*)d_out;

    const int zElems = in_sizes[0];        // B*D*H*W = 8388608
    const int nPoints = zElems / D;        // 131072
    const int nBlocks = nPoints / BLOCK;   // 1024

    long long lossOff = ((long long)out_size > (long long)zElems) ? (long long)zElems : -1;
    long long idxOff  = ((long long)out_size >= (long long)zElems + 1 + nPoints)
                            ? (long long)zElems + 1 : -1;

    cnorm_kernel<<<(K + 255) / 256, 256>>>(cb);
    vq_kernel<<<nBlocks, BLOCK>>>(z, cb, out, idxOff);
    loss_kernel<<<1, 512>>>(out, nBlocks, lossOff, 1.0f / (float)zElems);
}

// round 3
// speedup vs baseline: 1.3281x; 1.3281x over previous
#include <cuda_runtime.h>
#include <cstdint>

#define D       64
#define K       1024
#define HW      4096
#define TILE    128
#define PITCH   132          // tile row pitch in floats (16B-aligned, bank-rotating)
#define BLOCK   128
#define CHUNK   16
#define MAXBLK  4096

__device__ float g_cnorm[K];
__device__ float g_partials[MAXBLK];

typedef unsigned long long u64;

__device__ __forceinline__ u64 ffma2(u64 a, u64 b, u64 c) {
    u64 d;
    asm("fma.rn.f32x2 %0, %1, %2, %3;" : "=l"(d) : "l"(a), "l"(b), "l"(c));
    return d;
}
__device__ __forceinline__ u64 dup2(float v) {
    u64 r;
    asm("mov.b64 %0, {%1, %1};" : "=l"(r) : "f"(v));
    return r;
}
__device__ __forceinline__ float lo2(u64 v) {
    float a, b;
    asm("mov.b64 {%0, %1}, %2;" : "=f"(a), "=f"(b) : "l"(v));
    return a;
}
__device__ __forceinline__ float hi2(u64 v) {
    float a, b;
    asm("mov.b64 {%0, %1}, %2;" : "=f"(a), "=f"(b) : "l"(v));
    return b;
}

// ||c_k||^2, sequential mul-then-add; smem-staged for coalesced gmem reads.
__global__ void __launch_bounds__(64) cnorm_kernel(const float* __restrict__ cb) {
    __shared__ float sCb[64 * 65];
    const int tid = threadIdx.x;
    const float* src = cb + (size_t)blockIdx.x * 64 * D;
#pragma unroll
    for (int j = 0; j < 64; j++) {
        int idx = tid + j * 64;
        sCb[(idx >> 6) * 65 + (idx & 63)] = src[idx];
    }
    __syncthreads();
    float s = 0.f;
    const float* row = sCb + tid * 65;
#pragma unroll
    for (int d = 0; d < D; d++)
        s = __fadd_rn(s, __fmul_rn(row[d], row[d]));
    g_cnorm[blockIdx.x * 64 + tid] = s;
}

// One thread per point. Bit-exact emulation of
//   dist_k = fl( fl(znorm + cnorm_k) - fl(2 * dot_k) ), argmin = first min.
// dot_k: strictly sequential fma over d (per f32x2 lane). znorm: sequential
// mul-then-add. z held in smem column; 16 codes (8 f32x2 chains) per pass.
__global__ void __launch_bounds__(BLOCK, 3)
vq_kernel(const float* __restrict__ z,
          const float* __restrict__ cb,
          float* __restrict__ out,
          long long idxOff) {
    extern __shared__ float smem[];
    float* sZ   = smem;                       // [D][BLOCK]
    float* sCt  = smem + D * BLOCK;           // [D][PITCH] transposed tile
    float* sN   = sCt + D * PITCH;            // [TILE]
    float* sRed = sN + TILE;                  // [BLOCK/32]

    const int tid = threadIdx.x;
    const int n = blockIdx.x * BLOCK + tid;
    const int b = n >> 12;            // n / HW
    const int hw = n & (HW - 1);      // n % HW

    // Stage z into own smem column; compute znorm sequentially (ascending d).
    const float* zbase = z + (size_t)b * D * HW + hw;
    float* zcol = sZ + tid;
    float zn = 0.f;
#pragma unroll
    for (int d = 0; d < D; d++) {
        float v = zbase[(size_t)d * HW];
        zcol[(size_t)d * BLOCK] = v;
        zn = __fadd_rn(zn, __fmul_rn(v, v));
    }
    // No sync needed: each thread reads only its own column.

    float best = 3.4e38f;
    int bestk = 0;

#pragma unroll 1
    for (int t = 0; t < K / TILE; t++) {
        // Cooperative transposed tile load (gmem-coalesced).
        const float* src = cb + (size_t)t * TILE * D;
#pragma unroll
        for (int j = 0; j < (TILE * D) / BLOCK; j++) {
            int idx = tid + j * BLOCK;
            sCt[(idx & (D - 1)) * PITCH + (idx >> 6)] = src[idx];
        }
        sN[tid] = g_cnorm[t * TILE + tid];
        __syncthreads();

#pragma unroll 1
        for (int c0 = 0; c0 < TILE; c0 += CHUNK) {
            u64 A[CHUNK / 2];
#pragma unroll
            for (int i = 0; i < CHUNK / 2; i++) A[i] = 0ull;

#pragma unroll 8
            for (int d = 0; d < D; d++) {
                u64 zp = dup2(zcol[(size_t)d * BLOCK]);
                const float* row = sCt + d * PITCH + c0;
                ulonglong2 v0 = *(const ulonglong2*)(row);
                ulonglong2 v1 = *(const ulonglong2*)(row + 4);
                ulonglong2 v2 = *(const ulonglong2*)(row + 8);
                ulonglong2 v3 = *(const ulonglong2*)(row + 12);
                A[0] = ffma2(zp, v0.x, A[0]);
                A[1] = ffma2(zp, v0.y, A[1]);
                A[2] = ffma2(zp, v1.x, A[2]);
                A[3] = ffma2(zp, v1.y, A[3]);
                A[4] = ffma2(zp, v2.x, A[4]);
                A[5] = ffma2(zp, v2.y, A[5]);
                A[6] = ffma2(zp, v3.x, A[6]);
                A[7] = ffma2(zp, v3.y, A[7]);
            }
#pragma unroll
            for (int i = 0; i < CHUNK / 2; i++) {
                float d0 = lo2(A[i]);
                float d1 = hi2(A[i]);
                float t1 = __fadd_rn(zn, sN[c0 + 2 * i]);
                float dist = __fsub_rn(t1, __fmul_rn(2.0f, d0));
                if (dist < best) { best = dist; bestk = t * TILE + c0 + 2 * i; }
                float t2 = __fadd_rn(zn, sN[c0 + 2 * i + 1]);
                float dist2 = __fsub_rn(t2, __fmul_rn(2.0f, d1));
                if (dist2 < best) { best = dist2; bestk = t * TILE + c0 + 2 * i + 1; }
            }
        }
        __syncthreads();
    }

    // Gather chosen code; emulate z_q_st = fl(z + fl(z_q - z)); loss terms.
    const float4* crow = (const float4*)(cb + (size_t)bestk * D);
    float* outz = out + (size_t)b * D * HW + hw;
    float sumsq = 0.f;
#pragma unroll
    for (int i = 0; i < 16; i++) {
        float4 q = __ldg(&crow[i]);
        float qq[4] = {q.x, q.y, q.z, q.w};
#pragma unroll
        for (int j = 0; j < 4; j++) {
            float zv = zcol[(size_t)(4 * i + j) * BLOCK];
            float dd = __fsub_rn(qq[j], zv);
            float ov = __fadd_rn(zv, dd);
            sumsq += __fmul_rn(dd, dd);
            outz[(size_t)(4 * i + j) * HW] = ov;
        }
    }

    if (idxOff >= 0) out[idxOff + n] = (float)bestk;

    // Deterministic block reduction of sumsq.
#pragma unroll
    for (int off = 16; off > 0; off >>= 1)
        sumsq += __shfl_down_sync(0xffffffffu, sumsq, off);
    if ((tid & 31) == 0) sRed[tid >> 5] = sumsq;
    __syncthreads();
    if (tid == 0) {
        float tot = 0.f;
#pragma unroll
        for (int w = 0; w < BLOCK / 32; w++) tot += sRed[w];
        g_partials[blockIdx.x] = tot;
    }
}

__global__ void loss_kernel(float* __restrict__ out, int nBlocks,
                            long long lossOff, float invN) {
    __shared__ float s[512];
    int tid = threadIdx.x;
    float v = 0.f;
    for (int i = tid; i < nBlocks; i += 512) v += g_partials[i];
    s[tid] = v;
    __syncthreads();
    for (int st = 256; st > 0; st >>= 1) {
        if (tid < st) s[tid] += s[tid + st];
        __syncthreads();
    }
    if (tid == 0 && lossOff >= 0) {
        float m = __fmul_rn(s[0], invN);              // exact: invN = 2^-23
        out[lossOff] = __fadd_rn(m, __fmul_rn(0.25f, m));
    }
}

extern "C" void kernel_launch(void* const* d_in, const int* in_sizes, int n_in,
                              void* d_out, int out_size) {
    const float* z = (const float*)d_in[0];
    const float* cb = (const float*)d_in[1];
    float* out = (float*)d_out;

    const int zElems = in_sizes[0];        // B*D*H*W = 8388608
    const int nPoints = zElems / D;        // 131072
    const int nBlocks = nPoints / BLOCK;   // 1024

    long long lossOff = ((long long)out_size > (long long)zElems) ? (long long)zElems : -1;
    long long idxOff  = ((long long)out_size >= (long long)zElems + 1 + nPoints)
                            ? (long long)zElems + 1 : -1;

    const int smemBytes = (D * BLOCK + D * PITCH + TILE + BLOCK / 32) * 4;
    cudaFuncSetAttribute(vq_kernel, cudaFuncAttributeMaxDynamicSharedMemorySize,
                         smemBytes);

    cnorm_kernel<<<K / 64, 64>>>(cb);
    vq_kernel<<<nBlocks, BLOCK, smemBytes>>>(z, cb, out, idxOff);
    loss_kernel<<<1, 512>>>(out, nBlocks, lossOff, 1.0f / (float)zElems);
}

// round 5
// speedup vs baseline: 3.2148x; 2.4206x over previous
#include <cuda_runtime.h>
#include <cuda_bf16.h>
#include <cstdint>

typedef unsigned int u32;
typedef unsigned short u16;

#define D       64
#define K       1024
#define HW      4096
#define BLOCK   128
#define CHUNK   32
#define NCHUNKS (K / CHUNK)
#define CAPL    16
#define MAXBLK  4096

// dynamic smem layout (bytes)
#define OFF_Z    0          // fp32 z [64][128]      32768
#define OFF_CN   32768      // fp32 cn[1024]          4096
#define OFF_B0   36864      // u32 [32][36]           4608
#define OFF_B1   41472      // u32 [32][36]           4608
#define OFF_CAND 46080      // u16 [128][64]         16384
#define OFF_RED  62464      // fp32 [64]               256
#define SMEM_SZ  62720

__device__ float g_cnorm[K];
__device__ u32   g_cbpk[K * 32];   // bf16x2-packed codebook [code][dimpair]
__device__ float g_partials[MAXBLK];

__device__ __forceinline__ u32 bf2(float lo, float hi) {
    u32 r;
    asm("cvt.rn.bf16x2.f32 %0, %1, %2;" : "=r"(r) : "f"(hi), "f"(lo));
    return r;
}
__device__ __forceinline__ void mma16816(float c[4], const u32 a0, const u32 a1,
                                         const u32 a2, const u32 a3,
                                         const u32 b0, const u32 b1) {
    asm volatile(
        "mma.sync.aligned.m16n8k16.row.col.f32.bf16.bf16.f32 "
        "{%0,%1,%2,%3}, {%4,%5,%6,%7}, {%8,%9}, {%0,%1,%2,%3};"
        : "+f"(c[0]), "+f"(c[1]), "+f"(c[2]), "+f"(c[3])
        : "r"(a0), "r"(a1), "r"(a2), "r"(a3), "r"(b0), "r"(b1));
}

// ||c||^2 (bitwise-sequential) + bf16 packed codebook
__global__ void __launch_bounds__(64) cnorm_kernel(const float* __restrict__ cb) {
    __shared__ float sCb[64 * 65];
    const int tid = threadIdx.x;
    const float* src = cb + (size_t)blockIdx.x * 64 * D;
#pragma unroll
    for (int j = 0; j < 64; j++) {
        int idx = tid + j * 64;
        sCb[(idx >> 6) * 65 + (idx & 63)] = src[idx];
    }
    __syncthreads();
    const float* row = sCb + tid * 65;
    float s = 0.f;
#pragma unroll
    for (int d = 0; d < D; d++)
        s = __fadd_rn(s, __fmul_rn(row[d], row[d]));
    const int code = blockIdx.x * 64 + tid;
    g_cnorm[code] = s;
#pragma unroll
    for (int q = 0; q < 32; q++)
        g_cbpk[code * 32 + q] = bf2(row[2 * q], row[2 * q + 1]);
}

__global__ void __launch_bounds__(BLOCK, 3)
vq_kernel(const float* __restrict__ z,
          const float* __restrict__ cb,
          float* __restrict__ out,
          long long idxOff) {
    extern __shared__ char smem[];
    float* sZ = (float*)(smem + OFF_Z);
    float* sCn = (float*)(smem + OFF_CN);
    u16* sCand = (u16*)(smem + OFF_CAND);
    u32* sCandU = (u32*)(smem + OFF_CAND);
    float* sRed = (float*)(smem + OFF_RED);

    const int tid = threadIdx.x;
    const int w = tid >> 5;
    const int lane = tid & 31;
    const int g = lane >> 2;     // row group
    const int q = lane & 3;      // col group
    const int n = blockIdx.x * BLOCK + tid;
    const int b = n >> 12;
    const int hw = n & (HW - 1);

    // stage z (exact), znorm (bitwise sequential)
    const float* zbase = z + (size_t)b * D * HW + hw;
    float zn = 0.f;
#pragma unroll
    for (int d = 0; d < D; d++) {
        float v = zbase[(size_t)d * HW];
        sZ[d * BLOCK + tid] = v;
        zn = __fadd_rn(zn, __fmul_rn(v, v));
    }
#pragma unroll
    for (int j = 0; j < K / BLOCK; j++)
        sCn[tid + j * BLOCK] = g_cnorm[tid + j * BLOCK];
#pragma unroll
    for (int j = 0; j < 32; j++)
        sCandU[tid + j * BLOCK] = 0xFFFFFFFFu;
    u32 pf[8];
#pragma unroll
    for (int i = 0; i < 8; i++) pf[i] = g_cbpk[tid + 128 * i];
    __syncthreads();

    // A fragments: rows {g, g+8, g+16, g+24} of this warp's 32 points
    u32 aR[4][4][2];
#pragma unroll
    for (int i = 0; i < 4; i++) {
        const int p = 32 * w + 8 * i + g;
#pragma unroll
        for (int kt = 0; kt < 4; kt++)
#pragma unroll
            for (int h = 0; h < 2; h++) {
                const int k0 = 16 * kt + 8 * h + 2 * q;
                aR[i][kt][h] = bf2(sZ[k0 * BLOCK + p], sZ[(k0 + 1) * BLOCK + p]);
            }
    }

    // block max of cn and zn (for certified delta)
    float mx = 0.f, zm = zn;
#pragma unroll
    for (int j = 0; j < K / BLOCK; j++) mx = fmaxf(mx, sCn[tid + j * BLOCK]);
#pragma unroll
    for (int o = 16; o > 0; o >>= 1) {
        mx = fmaxf(mx, __shfl_xor_sync(0xffffffffu, mx, o));
        zm = fmaxf(zm, __shfl_xor_sync(0xffffffffu, zm, o));
    }
    if (lane == 0) { sRed[w] = mx; sRed[8 + w] = zm; }
    __syncthreads();
    mx = fmaxf(fmaxf(sRed[0], sRed[1]), fmaxf(sRed[2], sRed[3]));
    zm = fmaxf(fmaxf(sRed[8], sRed[9]), fmaxf(sRed[10], sRed[11]));

    const float delta = 0.0165f * sqrtf(zm * mx) + 1e-6f * (zm + mx + 1.0f);
    float rm[4] = {3.4e38f, 3.4e38f, 3.4e38f, 3.4e38f};
    int cnt4[4] = {0, 0, 0, 0};

#pragma unroll 1
    for (int t = 0; t < NCHUNKS; t++) {
        u32* bw = (u32*)(smem + ((t & 1) ? OFF_B1 : OFF_B0));
#pragma unroll
        for (int i = 0; i < 8; i++) {
            int idx = tid + 128 * i;
            bw[(idx >> 5) * 36 + (idx & 31)] = pf[i];
        }
        __syncthreads();
        if (t + 1 < NCHUNKS) {
#pragma unroll
            for (int i = 0; i < 8; i++)
                pf[i] = g_cbpk[(t + 1) * 1024 + tid + 128 * i];
        }
        const u32* br = bw;

        float cfr[2][4][4];
#pragma unroll
        for (int mt = 0; mt < 2; mt++)
#pragma unroll
            for (int nt = 0; nt < 4; nt++)
#pragma unroll
                for (int e = 0; e < 4; e++) cfr[mt][nt][e] = 0.f;

#pragma unroll
        for (int kt = 0; kt < 4; kt++) {
            u32 bb[4][2];
#pragma unroll
            for (int nt = 0; nt < 4; nt++) {
                const int base = (8 * nt + g) * 36 + q + 8 * kt;
                bb[nt][0] = br[base];
                bb[nt][1] = br[base + 4];
            }
#pragma unroll
            for (int mt = 0; mt < 2; mt++)
#pragma unroll
                for (int nt = 0; nt < 4; nt++)
                    mma16816(cfr[mt][nt],
                             aR[2 * mt][kt][0], aR[2 * mt + 1][kt][0],
                             aR[2 * mt][kt][1], aR[2 * mt + 1][kt][1],
                             bb[nt][0], bb[nt][1]);
        }

        // screen in registers
        const int cbase = t * CHUNK;
        float cnv[8];
#pragma unroll
        for (int nt = 0; nt < 4; nt++) {
            cnv[2 * nt] = sCn[cbase + 8 * nt + 2 * q];
            cnv[2 * nt + 1] = sCn[cbase + 8 * nt + 2 * q + 1];
        }
#pragma unroll
        for (int mt = 0; mt < 2; mt++)
#pragma unroll
            for (int hh = 0; hh < 2; hh++) {
                const int i = 2 * mt + hh;
                const int pidx = 32 * w + 8 * i + g;
#pragma unroll
                for (int nt = 0; nt < 4; nt++)
#pragma unroll
                    for (int e = 0; e < 2; e++) {
                        float s = __fmaf_rn(-2.0f, cfr[mt][nt][2 * hh + e],
                                            cnv[2 * nt + e]);
                        if (s <= rm[i] + delta) {
                            if (cnt4[i] < CAPL) {
                                int L = q * 16 + cnt4[i];
                                int phys = ((((L >> 1) + pidx) & 31) << 1) | (L & 1);
                                sCand[pidx * 64 + phys] =
                                    (u16)(cbase + 8 * nt + 2 * q + e);
                            }
                            cnt4[i]++;
                        }
                        rm[i] = fminf(rm[i], s);
                    }
            }
#pragma unroll
        for (int i = 0; i < 4; i++) {
            rm[i] = fminf(rm[i], __shfl_xor_sync(0xffffffffu, rm[i], 1));
            rm[i] = fminf(rm[i], __shfl_xor_sync(0xffffffffu, rm[i], 2));
        }
    }

    // overflow markers
#pragma unroll
    for (int i = 0; i < 4; i++)
        if (cnt4[i] > CAPL) {
            const int pidx = 32 * w + 8 * i + g;
            const int L = q * 16;
            const int phys = ((((L >> 1) + pidx) & 31) << 1) | (L & 1);
            sCand[pidx * 64 + phys] = (u16)0xFFFE;
        }
    __syncwarp();

    // bit-exact refine: sequential fma ascending d; first-min via (dist,k) lexicographic
    float best = 3.4e38f;
    int bestk = 0x7FFFFFFF;
    bool ovf = false;
#pragma unroll 1
    for (int s = 0; s < 32; s++) {
        u32 v = sCandU[tid * 32 + ((s + tid) & 31)];
#pragma unroll
        for (int h = 0; h < 2; h++) {
            u32 kk = (h == 0) ? (v & 0xFFFFu) : (v >> 16);
            if (kk >= 0xFFFEu) { if (kk == 0xFFFEu) ovf = true; continue; }
            const float4* crow = (const float4*)(cb + (size_t)kk * D);
            float dot = 0.f;
#pragma unroll
            for (int qd = 0; qd < 16; qd++) {
                float4 c4 = __ldg(&crow[qd]);
                dot = __fmaf_rn(sZ[(4 * qd + 0) * BLOCK + tid], c4.x, dot);
                dot = __fmaf_rn(sZ[(4 * qd + 1) * BLOCK + tid], c4.y, dot);
                dot = __fmaf_rn(sZ[(4 * qd + 2) * BLOCK + tid], c4.z, dot);
                dot = __fmaf_rn(sZ[(4 * qd + 3) * BLOCK + tid], c4.w, dot);
            }
            float dist = __fsub_rn(__fadd_rn(zn, sCn[kk]), __fmul_rn(2.0f, dot));
            if (dist < best || (dist == best && (int)kk < bestk)) {
                best = dist; bestk = (int)kk;
            }
        }
    }
    if (ovf) {
        best = 3.4e38f; bestk = 0;
#pragma unroll 1
        for (int kk = 0; kk < K; kk++) {
            const float4* crow = (const float4*)(cb + (size_t)kk * D);
            float dot = 0.f;
#pragma unroll
            for (int qd = 0; qd < 16; qd++) {
                float4 c4 = __ldg(&crow[qd]);
                dot = __fmaf_rn(sZ[(4 * qd + 0) * BLOCK + tid], c4.x, dot);
                dot = __fmaf_rn(sZ[(4 * qd + 1) * BLOCK + tid], c4.y, dot);
                dot = __fmaf_rn(sZ[(4 * qd + 2) * BLOCK + tid], c4.z, dot);
                dot = __fmaf_rn(sZ[(4 * qd + 3) * BLOCK + tid], c4.w, dot);
            }
            float dist = __fsub_rn(__fadd_rn(zn, sCn[kk]), __fmul_rn(2.0f, dot));
            if (dist < best) { best = dist; bestk = kk; }
        }
    }

    // epilogue (bitwise recipes from R3)
    const float4* qrow = (const float4*)(cb + (size_t)bestk * D);
    float* outz = out + (size_t)b * D * HW + hw;
    float sumsq = 0.f;
#pragma unroll
    for (int i = 0; i < 16; i++) {
        float4 qv = __ldg(&qrow[i]);
        float qq[4] = {qv.x, qv.y, qv.z, qv.w};
#pragma unroll
        for (int j = 0; j < 4; j++) {
            float zv = sZ[(4 * i + j) * BLOCK + tid];
            float dd = __fsub_rn(qq[j], zv);
            float ov = __fadd_rn(zv, dd);
            sumsq += __fmul_rn(dd, dd);
            outz[(size_t)(4 * i + j) * HW] = ov;
        }
    }
    if (idxOff >= 0) out[idxOff + n] = (float)bestk;

#pragma unroll
    for (int o = 16; o > 0; o >>= 1)
        sumsq += __shfl_down_sync(0xffffffffu, sumsq, o);
    __syncthreads();
    if (lane == 0) sRed[w] = sumsq;
    __syncthreads();
    if (tid == 0) {
        float tot = 0.f;
#pragma unroll
        for (int ww = 0; ww < BLOCK / 32; ww++) tot += sRed[ww];
        g_partials[blockIdx.x] = tot;
    }
}

__global__ void loss_kernel(float* __restrict__ out, int nBlocks,
                            long long lossOff, float invN) {
    __shared__ float s[512];
    int tid = threadIdx.x;
    float v = 0.f;
    for (int i = tid; i < nBlocks; i += 512) v += g_partials[i];
    s[tid] = v;
    __syncthreads();
    for (int st = 256; st > 0; st >>= 1) {
        if (tid < st) s[tid] += s[tid + st];
        __syncthreads();
    }
    if (tid == 0 && lossOff >= 0) {
        float m = __fmul_rn(s[0], invN);
        out[lossOff] = __fadd_rn(m, __fmul_rn(0.25f, m));
    }
}

extern "C" void kernel_launch(void* const* d_in, const int* in_sizes, int n_in,
                              void* d_out, int out_size) {
    const float* z = (const float*)d_in[0];
    const float* cb = (const float*)d_in[1];
    float* out = (float*)d_out;

    const int zElems = in_sizes[0];        // 8388608
    const int nPoints = zElems / D;        // 131072
    const int nBlocks = nPoints / BLOCK;   // 1024

    long long lossOff = ((long long)out_size > (long long)zElems) ? (long long)zElems : -1;
    long long idxOff  = ((long long)out_size >= (long long)zElems + 1 + nPoints)
                            ? (long long)zElems + 1 : -1;

    cudaFuncSetAttribute(vq_kernel, cudaFuncAttributeMaxDynamicSharedMemorySize,
                         SMEM_SZ);

    cnorm_kernel<<<K / 64, 64>>>(cb);
    vq_kernel<<<nBlocks, BLOCK, SMEM_SZ>>>(z, cb, out, idxOff);
    loss_kernel<<<1, 512>>>(out, nBlocks, lossOff, 1.0f / (float)zElems);
}